// round 2
// baseline (speedup 1.0000x reference)
#include <cuda_runtime.h>
#include <cstddef>

// Problem constants
#define VSZ   100000
#define DIM   256
#define NSEQ  8192
#define SLEN  20
#define HID   256
#define G4    1024           // 4*H
#define KTOT  512            // D + H

// ---------------------------------------------------------------------------
// Scratch (device globals only — no allocations allowed)
// ---------------------------------------------------------------------------
__device__ __align__(256) float g_Wt[2 * KTOT * G4];        // [dir][k][g]  4 MB
__device__ __align__(256) float g_h[2 * NSEQ * HID];        // hidden state 16.8 MB
__device__ __align__(256) float g_c[2 * NSEQ * HID];        // cell state   16.8 MB
__device__ __align__(256) float g_gates[2 * (size_t)NSEQ * G4]; // 67 MB
__device__ __align__(256) float g_acc[NSEQ];
__device__ int g_is64;

// ---------------------------------------------------------------------------
// Detect neigh_idx dtype (int32 vs int64). For genuine int64 data all values
// lie in [0, VSZ). int32 data read as int64 combines adjacent words and is
// >= 2^32 unless the odd word is exactly 0 (prob ~1e-5 per sample).
// Deterministic: same input -> same flag.
// ---------------------------------------------------------------------------
__global__ void detect_idx_kernel(const void* neigh) {
    const long long* p = (const long long*)neigh;
    int ok = 1;
    #pragma unroll
    for (int i = 0; i < 4; i++) {
        long long v = p[i];
        if (v < 0 || v >= (long long)VSZ) ok = 0;
    }
    g_is64 = ok;
}

// ---------------------------------------------------------------------------
// Zero h, c, acc
// ---------------------------------------------------------------------------
__global__ void prep_state_kernel() {
    int i = blockIdx.x * blockDim.x + threadIdx.x;
    int tot = 2 * NSEQ * HID;
    if (i < tot) { g_h[i] = 0.0f; g_c[i] = 0.0f; }
    if (i < NSEQ) g_acc[i] = 0.0f;
}

// ---------------------------------------------------------------------------
// Build Wt[dir][k][g]:  k < DIM -> w_ih[g][k],  else -> w_hh[g][k-DIM]
// (one-time 4MB transpose per launch; L2-bound, negligible)
// ---------------------------------------------------------------------------
__global__ void prep_weights_kernel(const float* __restrict__ wihf,
                                    const float* __restrict__ whhf,
                                    const float* __restrict__ wihb,
                                    const float* __restrict__ whhb) {
    int i = blockIdx.x * blockDim.x + threadIdx.x;
    if (i >= 2 * KTOT * G4) return;
    int dir = i / (KTOT * G4);
    int rem = i % (KTOT * G4);
    int k = rem / G4;
    int g = rem % G4;
    const float* wih = dir ? wihb : wihf;
    const float* whh = dir ? whhb : whhf;
    float v = (k < DIM) ? wih[g * DIM + k] : whh[g * HID + (k - DIM)];
    g_Wt[i] = v;
}

// ---------------------------------------------------------------------------
// Step GEMM: gates[dir][n][g] = sum_k A[n][k] * Wt[dir][k][g]
//   A[n][k] = k < DIM ? emb[idx(n, t_x)][k] : h[dir][n][k-DIM]
// Classic 128x128x8 SGEMM, 256 threads, 8x8 microtile, fused gather.
// ---------------------------------------------------------------------------
#define BM 128
#define BN 128
#define BK 8
#define TM 8
#define TN 8

__global__ __launch_bounds__(256, 2)
void lstm_gemm_kernel(const float* __restrict__ emb,
                      const void*  __restrict__ neigh,
                      int t) {
    const int dir = blockIdx.z;
    const int t_x = dir ? (SLEN - 1 - t) : t;

    __shared__ float As[BK][BM];
    __shared__ float Bs[BK][BN];

    const int tid = threadIdx.x;
    const int blockRow = blockIdx.y;
    const int blockCol = blockIdx.x;

    // A loader: each thread owns one row/float4 slot (128 rows * 2 float4)
    const int aRow  = tid >> 1;          // 0..127
    const int aCol4 = (tid & 1) * 4;     // 0 or 4
    const int n = blockRow * BM + aRow;

    long long idx;
    if (g_is64) idx = ((const long long*)neigh)[(long long)n * SLEN + t_x];
    else        idx = ((const int*)neigh)[n * SLEN + t_x];
    const float* aEmb = emb + (long long)idx * DIM;
    const float* aH   = g_h + ((size_t)dir * NSEQ + n) * HID;

    // B loader: 8 rows * 32 float4
    const int bRow  = tid >> 5;          // 0..7
    const int bCol4 = (tid & 31) * 4;    // 0..124
    const float* Wt = g_Wt + (size_t)dir * (KTOT * G4) + blockCol * BN;

    const int tr = tid >> 4;             // 0..15
    const int tc = tid & 15;             // 0..15

    float accv[TM][TN] = {};
    float regM[TM], regN[TN];

    for (int k0 = 0; k0 < KTOT; k0 += BK) {
        const int kA = k0 + aCol4;
        float4 av = (kA < DIM) ? *(const float4*)(aEmb + kA)
                               : *(const float4*)(aH + (kA - DIM));
        As[aCol4 + 0][aRow] = av.x;
        As[aCol4 + 1][aRow] = av.y;
        As[aCol4 + 2][aRow] = av.z;
        As[aCol4 + 3][aRow] = av.w;

        float4 bv = *(const float4*)(Wt + (size_t)(k0 + bRow) * G4 + bCol4);
        *(float4*)&Bs[bRow][bCol4] = bv;
        __syncthreads();

        #pragma unroll
        for (int k = 0; k < BK; k++) {
            #pragma unroll
            for (int m = 0; m < TM; m++) regM[m] = As[k][tr * TM + m];
            #pragma unroll
            for (int q = 0; q < TN; q++) regN[q] = Bs[k][tc * TN + q];
            #pragma unroll
            for (int m = 0; m < TM; m++)
                #pragma unroll
                for (int q = 0; q < TN; q++)
                    accv[m][q] += regM[m] * regN[q];
        }
        __syncthreads();
    }

    float* out = g_gates + (size_t)dir * NSEQ * G4
               + (size_t)(blockRow * BM + tr * TM) * G4
               + blockCol * BN + tc * TN;
    #pragma unroll
    for (int m = 0; m < TM; m++) {
        float4 v0 = make_float4(accv[m][0], accv[m][1], accv[m][2], accv[m][3]);
        float4 v1 = make_float4(accv[m][4], accv[m][5], accv[m][6], accv[m][7]);
        *(float4*)(out + (size_t)m * G4)     = v0;
        *(float4*)(out + (size_t)m * G4 + 4) = v1;
    }
}

// ---------------------------------------------------------------------------
// Pointwise gates + state update + per-sequence accumulation.
// One block per sequence, 256 threads (one per hidden unit), both directions.
// PyTorch gate order: i, f, g, o.
// ---------------------------------------------------------------------------
__global__ __launch_bounds__(256)
void lstm_point_kernel(const float* __restrict__ bf,
                       const float* __restrict__ bb) {
    const int n = blockIdx.x;
    const int j = threadIdx.x;
    float s_local = 0.0f;

    #pragma unroll
    for (int dir = 0; dir < 2; dir++) {
        const float* b = dir ? bb : bf;
        const float* g = g_gates + (size_t)dir * NSEQ * G4 + (size_t)n * G4;
        float gi = g[j]           + b[j];
        float gf = g[j + 256]     + b[j + 256];
        float gg = g[j + 512]     + b[j + 512];
        float go = g[j + 768]     + b[j + 768];
        size_t hidx = (size_t)dir * NSEQ * HID + (size_t)n * HID + j;
        float c = g_c[hidx];
        float si = 1.0f / (1.0f + __expf(-gi));
        float sf = 1.0f / (1.0f + __expf(-gf));
        float so = 1.0f / (1.0f + __expf(-go));
        float cn = sf * c + si * tanhf(gg);
        float hn = so * tanhf(cn);
        g_c[hidx] = cn;
        g_h[hidx] = hn;
        s_local += hn;
    }

    __shared__ float red[256];
    red[j] = s_local;
    __syncthreads();
    #pragma unroll
    for (int st = 128; st > 0; st >>= 1) {
        if (j < st) red[j] += red[j + st];
        __syncthreads();
    }
    if (j == 0) g_acc[n] += red[0];
}

// ---------------------------------------------------------------------------
// out[n][j] = acc[n] / (2H)   for all j in [0, 2H)
// ---------------------------------------------------------------------------
__global__ void final_kernel(float* __restrict__ out) {
    int i = blockIdx.x * blockDim.x + threadIdx.x;
    if (i < NSEQ * 512) out[i] = g_acc[i >> 9] * (1.0f / 512.0f);
}

// ---------------------------------------------------------------------------
// Launch
// ---------------------------------------------------------------------------
extern "C" void kernel_launch(void* const* d_in, const int* in_sizes, int n_in,
                              void* d_out, int out_size) {
    const float* emb   = (const float*)d_in[0];
    const float* wih_f = (const float*)d_in[1];
    const float* whh_f = (const float*)d_in[2];
    const float* b_f   = (const float*)d_in[3];
    const float* wih_b = (const float*)d_in[4];
    const float* whh_b = (const float*)d_in[5];
    const float* b_b   = (const float*)d_in[6];
    const void*  neigh = d_in[7];
    float* out = (float*)d_out;

    detect_idx_kernel<<<1, 1>>>(neigh);

    {
        int tot = 2 * NSEQ * HID;
        prep_state_kernel<<<(tot + 255) / 256, 256>>>();
    }
    {
        int tot = 2 * KTOT * G4;
        prep_weights_kernel<<<(tot + 255) / 256, 256>>>(wih_f, whh_f, wih_b, whh_b);
    }

    dim3 gemm_grid(G4 / BN, NSEQ / BM, 2);   // (8, 64, 2)
    for (int t = 0; t < SLEN; t++) {
        lstm_gemm_kernel<<<gemm_grid, 256>>>(emb, neigh, t);
        lstm_point_kernel<<<NSEQ, 256>>>(b_f, b_b);
    }

    final_kernel<<<(NSEQ * 512 + 255) / 256, 256>>>(out);
}